// round 1
// baseline (speedup 1.0000x reference)
#include <cuda_runtime.h>

// ---------------------------------------------------------------------------
// YOLOv3 loss. Inputs (metadata order):
//  0: p0 [B,255,13,13] f32   1: p1 [B,255,26,26] f32   2: p2 [B,255,52,52] f32
//  3: targets [B,N,5] f32    4: gt_valid [B,N] (bool/u8, i32 or f32 — detected)
//  5: anchors [9,2] f32
// Output: scalar f32.
// ---------------------------------------------------------------------------

#define A_PER 3
#define NCLS 80
#define MAXB 32
#define MAX_CELLS (MAXB * 3 * (13*13 + 26*26 + 52*52))   // 340,704 for B=32

__device__ int           g_mode;                 // 0=f32, 1=i32, 2=u8
__device__ double        g_acc[2];               // [loss, num_pos]
__device__ int           g_winner[MAX_CELLS];
__device__ unsigned char g_ignore[MAX_CELLS];

__device__ __forceinline__ float softplusf(float x) {
    return fmaxf(x, 0.f) + log1pf(expf(-fabsf(x)));
}
__device__ __forceinline__ float bcef(float x, float t) {
    return softplusf(x) - x * t;
}
__device__ __forceinline__ bool is_valid(const void* gv, int idx, int mode) {
    if (mode == 0) return ((const float*)gv)[idx] != 0.f;
    if (mode == 1) return ((const int*)gv)[idx]   != 0;
    return ((const unsigned char*)gv)[idx] != 0;
}

// --- K0: classify gt_valid dtype + zero accumulators -----------------------
__global__ void k_classify(const unsigned char* gv, int n_elems) {
    __shared__ int flags[2];  // [has3f, hasOddNonzero]
    if (threadIdx.x == 0) { flags[0] = 0; flags[1] = 0; }
    __syncthreads();
    for (int p = threadIdx.x; p < n_elems; p += blockDim.x) {
        unsigned char v = gv[p];
        if (v == 0x3F) atomicOr(&flags[0], 1);
        if ((p & 3) != 0 && v != 0) atomicOr(&flags[1], 1);
    }
    __syncthreads();
    if (threadIdx.x == 0) {
        g_mode = flags[0] ? 0 : (flags[1] ? 2 : 1);
        g_acc[0] = 0.0;
        g_acc[1] = 0.0;
    }
}

// --- K1: clear scratch ------------------------------------------------------
__global__ void k_clear(int total_cells) {
    int i = blockIdx.x * blockDim.x + threadIdx.x;
    if (i < total_cells) {
        g_winner[i] = -1;
        g_ignore[i] = 0;
    }
}

// --- K2: per-target scatter (winner via atomicMax, ignore flags) -----------
__global__ void k_targets(const float* __restrict__ targets,
                          const void*  __restrict__ gv,
                          const float* __restrict__ anchors,
                          int B, int N) {
    int tid = blockIdx.x * blockDim.x + threadIdx.x;
    int total = 3 * B * N;
    if (tid >= total) return;
    int s = tid / (B * N);
    int r = tid % (B * N);
    int b = r / N, n = r % N;
    if (!is_valid(gv, b * N + n, g_mode)) return;

    const float* tg = targets + (size_t)(b * N + n) * 5;
    float gx = tg[0], gy = tg[1], gw = tg[2], gh = tg[3];

    int H = (s == 0) ? 13 : (s == 1) ? 26 : 52;
    int off = (s == 0) ? 0
            : (s == 1) ? B * 3 * 169
                       : B * 3 * (169 + 676);
    int HW = H * H;

    float ious[3];
    float best_iou = -1.f; int best = 0;
    #pragma unroll
    for (int j = 0; j < 3; j++) {
        int ai = (2 - s) * 3 + j;                     // ANCHOR_MASKS
        float aw = anchors[ai * 2 + 0] * (1.f / 416.f);
        float ah = anchors[ai * 2 + 1] * (1.f / 416.f);
        float inter = fminf(gw, aw) * fminf(gh, ah);
        float uni   = gw * gh + aw * ah - inter + 1e-16f;
        float iou   = inter / uni;
        ious[j] = iou;
        if (iou > best_iou) { best_iou = iou; best = j; }  // first-max wins (argmax)
    }

    int gi = min((int)(gx * H), H - 1);
    int gj = min((int)(gy * H), H - 1);

    atomicMax(&g_winner[off + (b * 3 + best) * HW + gj * H + gi], n);
    #pragma unroll
    for (int j = 0; j < 3; j++)
        if (ious[j] > 0.5f)
            g_ignore[off + (b * 3 + j) * HW + gj * H + gi] = 1;
}

// --- K3: per-cell loss ------------------------------------------------------
__global__ void k_cells(const float* __restrict__ p0,
                        const float* __restrict__ p1,
                        const float* __restrict__ p2,
                        const float* __restrict__ targets,
                        const float* __restrict__ anchors,
                        int B, int N) {
    int idx = blockIdx.x * blockDim.x + threadIdx.x;
    int c0 = B * 3 * 169, c1 = B * 3 * 676, c2 = B * 3 * 2704;
    int total = c0 + c1 + c2;

    double loss = 0.0, npos = 0.0;
    if (idx < total) {
        int s, local, H;
        const float* pred;
        if (idx < c0)            { s = 0; local = idx;            H = 13; pred = p0; }
        else if (idx < c0 + c1)  { s = 1; local = idx - c0;       H = 26; pred = p1; }
        else                     { s = 2; local = idx - c0 - c1;  H = 52; pred = p2; }
        int HW = H * H;
        int i  = local % H;
        int t1 = local / H;
        int j  = t1 % H;  t1 /= H;
        int a  = t1 % 3;
        int b  = t1 / 3;

        size_t base = ((size_t)(b * 255 + a * 85)) * HW + (size_t)j * H + i;
        float conf = pred[base + (size_t)4 * HW];

        int wn = g_winner[idx];
        if (wn >= 0) {
            const float* tg = targets + (size_t)(b * N + wn) * 5;
            float gx = tg[0], gy = tg[1], gw = tg[2], gh = tg[3];
            int gcls = (int)tg[4];
            int ai = (2 - s) * 3 + a;
            float aw = anchors[ai * 2 + 0] * (1.f / 416.f);
            float ah = anchors[ai * 2 + 1] * (1.f / 416.f);
            float tx = gx * H - i;
            float ty = gy * H - j;
            float tw = logf(gw / aw);
            float th = logf(gh / ah);

            float px = pred[base];
            float py = pred[base + (size_t)1 * HW];
            float pw = pred[base + (size_t)2 * HW];
            float ph = pred[base + (size_t)3 * HW];

            float lcoord = bcef(px, tx) + bcef(py, ty)
                         + (pw - tw) * (pw - tw) + (ph - th) * (ph - th);
            float lsum = 5.0f * lcoord + softplusf(-conf);

            float lcls = 0.f;
            #pragma unroll 4
            for (int c = 0; c < NCLS; c++) {
                float pc = pred[base + (size_t)(5 + c) * HW];
                lcls += bcef(pc, (c == gcls) ? 1.f : 0.f);
            }
            loss = (double)(lsum + lcls);
            npos = 1.0;
        } else if (!g_ignore[idx]) {
            loss = 0.5 * (double)softplusf(conf);
        }
    }

    // block reduction -> global double accumulators
    __shared__ double sl[256], sn[256];
    int t = threadIdx.x;
    sl[t] = loss; sn[t] = npos;
    __syncthreads();
    for (int stride = 128; stride > 0; stride >>= 1) {
        if (t < stride) { sl[t] += sl[t + stride]; sn[t] += sn[t + stride]; }
        __syncthreads();
    }
    if (t == 0) {
        atomicAdd(&g_acc[0], sl[0]);
        atomicAdd(&g_acc[1], sn[0]);
    }
}

// --- K4: finalize -----------------------------------------------------------
__global__ void k_final(float* out, int B) {
    double l = g_acc[0], n = g_acc[1];
    out[0] = (float)((n > 0.0) ? l / n : l / (double)B);
}

extern "C" void kernel_launch(void* const* d_in, const int* in_sizes, int n_in,
                              void* d_out, int out_size) {
    const float* p0      = (const float*)d_in[0];
    const float* p1      = (const float*)d_in[1];
    const float* p2      = (const float*)d_in[2];
    const float* targets = (const float*)d_in[3];
    const void*  gvalid  = (const void*)d_in[4];
    const float* anchors = (const float*)d_in[5];
    float* out = (float*)d_out;

    int B = in_sizes[0] / (255 * 13 * 13);
    int N = in_sizes[3] / (B * 5);
    if (B > MAXB) B = MAXB;  // scratch bound (shapes are fixed B=32)

    int total_cells = B * 3 * (169 + 676 + 2704);
    int tgt_items   = 3 * B * N;

    k_classify<<<1, 64>>>((const unsigned char*)gvalid, B * N);
    k_clear<<<(total_cells + 255) / 256, 256>>>(total_cells);
    k_targets<<<(tgt_items + 127) / 128, 128>>>(targets, gvalid, anchors, B, N);
    k_cells<<<(total_cells + 255) / 256, 256>>>(p0, p1, p2, targets, anchors, B, N);
    k_final<<<1, 1>>>(out, B);
}

// round 2
// speedup vs baseline: 1.7106x; 1.7106x over previous
#include <cuda_runtime.h>

// ---------------------------------------------------------------------------
// YOLOv3 loss. Inputs (metadata order):
//  0: p0 [B,255,13,13] f32   1: p1 [B,255,26,26] f32   2: p2 [B,255,52,52] f32
//  3: targets [B,N,5] f32    4: gt_valid [B,N] (dtype runtime-detected)
//  5: anchors [9,2] f32
// Output: scalar f32.
//
// Strategy: dense noobj sum over ALL cells (no per-cell winner lookup),
// then a sparse correction pass over a compact list of cells touched by
// targets (positive cells: add coord/obj/cls losses and remove their noobj
// term; ignore-only cells: remove their noobj term).
// ---------------------------------------------------------------------------

#define NCLS 80
#define MAXB 32
#define MAX_CELLS (MAXB * 3 * (13*13 + 26*26 + 52*52))   // 340,704
#define MAX_TOUCH (3 * 3 * MAXB * 32)                    // >= 3 cells/target/scale

__device__ int    g_mode;                 // 0=f32, 1=i32, 2=u8
__device__ double g_acc[2];               // [loss, num_pos]
__device__ int    g_winner[MAX_CELLS];    // -1 or winning target n
__device__ int    g_touch[MAX_CELLS];     // dedup flag
__device__ int    g_cnt;                  // touched-cell count
__device__ int    g_list[MAX_TOUCH];      // packed (s,b,a,j,i)

// fast softplus: 2 MUFU ops; rel err ~1e-5 (budget is 1e-3 on the total)
__device__ __forceinline__ float sp(float x) {
    return fmaxf(x, 0.f) + __logf(1.f + __expf(-fabsf(x)));
}
__device__ __forceinline__ float bcef(float x, float t) {
    return sp(x) - x * t;
}
__device__ __forceinline__ bool is_valid(const void* gv, int idx, int mode) {
    if (mode == 0) return ((const float*)gv)[idx] != 0.f;
    if (mode == 1) return ((const int*)gv)[idx]   != 0;
    return ((const unsigned char*)gv)[idx] != 0;
}
__device__ __forceinline__ float warp_sum(float v) {
    #pragma unroll
    for (int o = 16; o; o >>= 1) v += __shfl_xor_sync(0xffffffffu, v, o);
    return v;
}

// --- K0: clear scratch; block 0 additionally classifies gt_valid dtype -----
__global__ void k_init(const unsigned char* gv, int n_bytes_elems, int total_cells) {
    int i = blockIdx.x * blockDim.x + threadIdx.x;
    if (i < total_cells) { g_winner[i] = -1; g_touch[i] = 0; }
    if (blockIdx.x == 0) {
        __shared__ int flags[2];
        if (threadIdx.x == 0) { flags[0] = 0; flags[1] = 0; }
        __syncthreads();
        for (int p = threadIdx.x; p < n_bytes_elems; p += blockDim.x) {
            unsigned char v = gv[p];
            if (v == 0x3F) atomicOr(&flags[0], 1);
            if ((p & 3) != 0 && v != 0) atomicOr(&flags[1], 1);
        }
        __syncthreads();
        if (threadIdx.x == 0) {
            g_mode = flags[0] ? 0 : (flags[1] ? 2 : 1);
            g_acc[0] = 0.0; g_acc[1] = 0.0; g_cnt = 0;
        }
    }
}

// --- K1: per-target scatter: winner via atomicMax; touched-cell list -------
__device__ __forceinline__ void touch_cell(int cell, int packed) {
    if (atomicExch(&g_touch[cell], 1) == 0) {
        int p = atomicAdd(&g_cnt, 1);
        g_list[p] = packed;
    }
}

__global__ void k_targets(const float* __restrict__ targets,
                          const void*  __restrict__ gv,
                          const float* __restrict__ anchors,
                          int B, int N) {
    int tid = blockIdx.x * blockDim.x + threadIdx.x;
    int total = 3 * B * N;
    if (tid >= total) return;
    int s = tid / (B * N);
    int r = tid % (B * N);
    int b = r / N, n = r % N;
    if (!is_valid(gv, b * N + n, g_mode)) return;

    const float* tg = targets + (size_t)(b * N + n) * 5;
    float gx = tg[0], gy = tg[1], gw = tg[2], gh = tg[3];

    int H  = (s == 0) ? 13 : (s == 1) ? 26 : 52;
    int off = (s == 0) ? 0 : (s == 1) ? B * 3 * 169 : B * 3 * (169 + 676);
    int HW = H * H;

    float ious[3];
    float best_iou = -1.f; int best = 0;
    #pragma unroll
    for (int j = 0; j < 3; j++) {
        int ai = (2 - s) * 3 + j;                      // ANCHOR_MASKS
        float aw = anchors[ai * 2 + 0] * (1.f / 416.f);
        float ah = anchors[ai * 2 + 1] * (1.f / 416.f);
        float inter = fminf(gw, aw) * fminf(gh, ah);
        float uni   = gw * gh + aw * ah - inter + 1e-16f;
        float iou   = inter / uni;
        ious[j] = iou;
        if (iou > best_iou) { best_iou = iou; best = j; }
    }

    int gi = min((int)(gx * H), H - 1);
    int gj = min((int)(gy * H), H - 1);

    // pack (s,b,a,j,i): s:2 b:6 a:2 j:6 i:6
    int pbase = (s << 20) | (b << 14) | (gj << 6) | gi;

    int wcell = off + (b * 3 + best) * HW + gj * H + gi;
    atomicMax(&g_winner[wcell], n);
    touch_cell(wcell, pbase | (best << 12));
    #pragma unroll
    for (int j = 0; j < 3; j++) {
        if (ious[j] > 0.5f && j != best) {
            int cell = off + (b * 3 + j) * HW + gj * H + gi;
            touch_cell(cell, pbase | (j << 12));
        }
    }
    if (ious[best] > 0.5f) { /* winner cell already touched */ }
}

// --- K2: dense noobj sum over ALL cells (no winner/ignore reads) -----------
__global__ void k_noobj(const float* __restrict__ p0,
                        const float* __restrict__ p1,
                        const float* __restrict__ p2,
                        int B) {
    int t  = blockIdx.x * blockDim.x + threadIdx.x;
    int q1 = B * 3 * 169;     // scale-1 quad count == scale-0 element count
    int Q  = B * 3 * 845;     // scale-1 + scale-2 quads
    float sum = 0.f;
    if (t < Q) {
        if (t < q1) {
            int r = t / 169, qi = t % 169;
            size_t row = (size_t)((r / 3) * 255 + (r % 3) * 85 + 4);
            float4 v = *(const float4*)(p1 + row * 676 + qi * 4);
            sum = sp(v.x) + sp(v.y) + sp(v.z) + sp(v.w);
            sum += sp(p0[row * 169 + qi]);            // one scale-0 scalar
        } else {
            int u = t - q1;
            int r = u / 676, qi = u % 676;
            size_t row = (size_t)((r / 3) * 255 + (r % 3) * 85 + 4);
            float4 v = *(const float4*)(p2 + row * 2704 + qi * 4);
            sum = sp(v.x) + sp(v.y) + sp(v.z) + sp(v.w);
        }
    }
    sum = warp_sum(sum);
    __shared__ float ws[8];
    int lane = threadIdx.x & 31, w = threadIdx.x >> 5;
    if (lane == 0) ws[w] = sum;
    __syncthreads();
    if (threadIdx.x == 0) {
        float b = 0.f;
        #pragma unroll
        for (int i = 0; i < 8; i++) b += ws[i];
        atomicAdd(&g_acc[0], 0.5 * (double)b);
    }
}

// --- K3: sparse correction, one warp per touched cell ----------------------
__global__ void k_pos(const float* __restrict__ p0,
                      const float* __restrict__ p1,
                      const float* __restrict__ p2,
                      const float* __restrict__ targets,
                      const float* __restrict__ anchors,
                      int B, int N) {
    int gw_id = (blockIdx.x * blockDim.x + threadIdx.x) >> 5;
    int lane  = threadIdx.x & 31;
    int cnt   = g_cnt;

    double contrib = 0.0, np = 0.0;
    if (gw_id < cnt) {
        int pk = g_list[gw_id];
        int s = (pk >> 20) & 3, b = (pk >> 14) & 63;
        int a = (pk >> 12) & 3, j = (pk >> 6) & 63, i = pk & 63;
        int H  = (s == 0) ? 13 : (s == 1) ? 26 : 52;
        int off = (s == 0) ? 0 : (s == 1) ? B * 3 * 169 : B * 3 * (169 + 676);
        int HW = H * H;
        const float* pred = (s == 0) ? p0 : (s == 1) ? p1 : p2;
        int cell = off + (b * 3 + a) * HW + j * H + i;
        size_t base = ((size_t)(b * 255 + a * 85)) * HW + (size_t)j * H + i;

        int wn = g_winner[cell];
        float conf = pred[base + (size_t)4 * HW];     // broadcast load

        if (wn >= 0) {
            const float* tg = targets + (size_t)(b * N + wn) * 5;
            int gcls = (int)tg[4];
            // class loss: lanes cover classes lane, lane+32, lane+64
            float lcls = 0.f;
            #pragma unroll
            for (int c = lane; c < NCLS; c += 32) {
                float pc = pred[base + (size_t)(5 + c) * HW];
                lcls += bcef(pc, (c == gcls) ? 1.f : 0.f);
            }
            lcls = warp_sum(lcls);
            if (lane == 0) {
                float gx = tg[0], gy = tg[1], gww = tg[2], ghh = tg[3];
                int ai = (2 - s) * 3 + a;
                float aw = anchors[ai * 2 + 0] * (1.f / 416.f);
                float ah = anchors[ai * 2 + 1] * (1.f / 416.f);
                float tx = gx * H - i, ty = gy * H - j;
                float tw = logf(gww / aw), th = logf(ghh / ah);
                float px = pred[base];
                float py = pred[base + (size_t)1 * HW];
                float pw = pred[base + (size_t)2 * HW];
                float ph = pred[base + (size_t)3 * HW];
                float lcoord = bcef(px, tx) + bcef(py, ty)
                             + (pw - tw) * (pw - tw) + (ph - th) * (ph - th);
                contrib = (double)(5.0f * lcoord + sp(-conf) + lcls)
                        - 0.5 * (double)sp(conf);     // remove dense noobj term
                np = 1.0;
            }
        } else if (lane == 0) {
            contrib = -0.5 * (double)sp(conf);        // ignore-only cell
        }
    }

    // block-level accumulation: 8 warps -> 1 atomic pair
    __shared__ double sl[8], sn[8];
    int w = threadIdx.x >> 5;
    if (lane == 0) { sl[w] = contrib; sn[w] = np; }
    __syncthreads();
    if (threadIdx.x == 0) {
        double L = 0.0, P = 0.0;
        #pragma unroll
        for (int k = 0; k < 8; k++) { L += sl[k]; P += sn[k]; }
        if (L != 0.0) atomicAdd(&g_acc[0], L);
        if (P != 0.0) atomicAdd(&g_acc[1], P);
    }
}

// --- K4: finalize -----------------------------------------------------------
__global__ void k_final(float* out, int B) {
    double l = g_acc[0], n = g_acc[1];
    out[0] = (float)((n > 0.0) ? l / n : l / (double)B);
}

extern "C" void kernel_launch(void* const* d_in, const int* in_sizes, int n_in,
                              void* d_out, int out_size) {
    const float* p0      = (const float*)d_in[0];
    const float* p1      = (const float*)d_in[1];
    const float* p2      = (const float*)d_in[2];
    const float* targets = (const float*)d_in[3];
    const void*  gvalid  = (const void*)d_in[4];
    const float* anchors = (const float*)d_in[5];
    float* out = (float*)d_out;

    int B = in_sizes[0] / (255 * 13 * 13);
    int N = in_sizes[3] / (B * 5);
    if (B > MAXB) B = MAXB;   // scratch bound (shapes fixed at B=32)

    int total_cells = B * 3 * (169 + 676 + 2704);
    int tgt_items   = 3 * B * N;
    int noobj_thr   = B * 3 * 845;                    // vector quads
    int max_touch   = 3 * 3 * B * N;                  // hard bound on list

    k_init   <<<(total_cells + 255) / 256, 256>>>((const unsigned char*)gvalid, B * N, total_cells);
    k_targets<<<(tgt_items + 127) / 128, 128>>>(targets, gvalid, anchors, B, N);
    k_noobj  <<<(noobj_thr + 255) / 256, 256>>>(p0, p1, p2, B);
    k_pos    <<<(max_touch * 32 + 255) / 256, 256>>>(p0, p1, p2, targets, anchors, B, N);
    k_final  <<<1, 1>>>(out, B);
}

// round 5
// speedup vs baseline: 2.1272x; 1.2435x over previous
#include <cuda_runtime.h>

// ---------------------------------------------------------------------------
// YOLOv3 loss — 2-launch version.
// Inputs: 0:p0[B,255,13,13] 1:p1[B,255,26,26] 2:p2[B,255,52,52] (f32)
//         3:targets[B,N,5] f32  4:gt_valid[B,N] (dtype auto)  5:anchors[9,2]
// Output: scalar f32.
//
// Invariant-based scratch: g_winner (n+1, 0=none) and g_bits dedup bitmask are
// zero at entry (zero-init at load; restored by k_fused each call), so no
// large clear pass is ever needed.
// ---------------------------------------------------------------------------

#define NCLS 80
#define MAXB 32
#define MAX_CELLS (MAXB * 3 * (13*13 + 26*26 + 52*52))   // 340,704
#define MAX_TOUCH (3 * 3 * MAXB * 32)                    // 5760

__device__ double       g_acc[2];                    // [loss, num_pos] (zero at entry)
__device__ int          g_cnt;                       // touched-cell count (zero at entry)
__device__ int          g_done;                      // block done counter (zero at entry)
__device__ int          g_winner[MAX_CELLS];         // 0=none else n+1 (zero at entry)
__device__ unsigned int g_bits[(MAX_CELLS + 31) / 32];// dedup bitmask (zero at entry)
__device__ int          g_list[MAX_TOUCH];           // packed (s,b,a,j,i)

__device__ __forceinline__ float sp(float x) {       // fast softplus, ~1e-5 rel err
    return fmaxf(x, 0.f) + __logf(1.f + __expf(-fabsf(x)));
}
__device__ __forceinline__ float bcef(float x, float t) { return sp(x) - x * t; }
__device__ __forceinline__ float warp_sum(float v) {
    #pragma unroll
    for (int o = 16; o; o >>= 1) v += __shfl_xor_sync(0xffffffffu, v, o);
    return v;
}

// ===========================================================================
// K1: per-target scatter. Each block first classifies gt_valid dtype from the
// raw bytes (B*N elements — L2 resident), then scatters winner + touch list.
// ===========================================================================
__global__ void __launch_bounds__(128)
k_targets(const float* __restrict__ targets,
          const unsigned char* __restrict__ gv,
          const float* __restrict__ anchors,
          int B, int N) {
    __shared__ int flags[2];                     // [saw 0x3F byte, saw nonzero at p%4!=0]
    if (threadIdx.x < 2) flags[threadIdx.x] = 0;
    __syncthreads();
    for (int p = threadIdx.x; p < B * N; p += blockDim.x) {
        unsigned char v = gv[p];
        if (v == 0x3F) atomicOr(&flags[0], 1);
        if ((p & 3) != 0 && v != 0) atomicOr(&flags[1], 1);
    }
    __syncthreads();
    int mode = flags[0] ? 0 : (flags[1] ? 2 : 1);  // 0=f32 1=i32 2=u8

    int tid = blockIdx.x * blockDim.x + threadIdx.x;
    int total = 3 * B * N;
    if (tid >= total) return;
    int s = tid / (B * N);
    int r = tid % (B * N);
    int b = r / N, n = r % N;

    bool valid;
    if (mode == 0)      valid = ((const float*)gv)[b * N + n] != 0.f;
    else if (mode == 1) valid = ((const int*)gv)[b * N + n]   != 0;
    else                valid = gv[b * N + n] != 0;
    if (!valid) return;

    const float* tg = targets + (size_t)(b * N + n) * 5;
    float gx = tg[0], gy = tg[1], gw = tg[2], gh = tg[3];

    int H   = (s == 0) ? 13 : (s == 1) ? 26 : 52;
    int off = (s == 0) ? 0 : (s == 1) ? B * 3 * 169 : B * 3 * (169 + 676);
    int HW  = H * H;

    float ious[3];
    float best_iou = -1.f; int best = 0;
    #pragma unroll
    for (int j = 0; j < 3; j++) {
        int ai = (2 - s) * 3 + j;                        // ANCHOR_MASKS
        float aw = anchors[ai * 2 + 0] * (1.f / 416.f);
        float ah = anchors[ai * 2 + 1] * (1.f / 416.f);
        float inter = fminf(gw, aw) * fminf(gh, ah);
        float uni   = gw * gh + aw * ah - inter + 1e-16f;
        float iou   = inter / uni;
        ious[j] = iou;
        if (iou > best_iou) { best_iou = iou; best = j; }
    }

    int gi = min((int)(gx * H), H - 1);
    int gj = min((int)(gy * H), H - 1);
    int pbase = (s << 20) | (b << 14) | (gj << 6) | gi;  // s:2 b:6 a:2 j:6 i:6

    #pragma unroll
    for (int j = 0; j < 3; j++) {
        bool is_best = (j == best);
        if (is_best || ious[j] > 0.5f) {
            int cell = off + (b * 3 + j) * HW + gj * H + gi;
            if (is_best) atomicMax(&g_winner[cell], n + 1);
            unsigned int m = 1u << (cell & 31);
            if ((atomicOr(&g_bits[cell >> 5], m) & m) == 0) {
                int p = atomicAdd(&g_cnt, 1);
                g_list[p] = pbase | (j << 12);
            }
        }
    }
}

// ===========================================================================
// K2: fused dense-noobj + sparse-correction + finalize.
//   blocks [0, nDense)        : vectorized 0.5*softplus(conf) over all cells
//   blocks [nDense, nDense+S) : one warp per touched cell (correction +
//                               scratch invariant restore)
//   last finished block       : writes out[0], resets acc/cnt/done
// ===========================================================================
__global__ void __launch_bounds__(256, 8)
k_fused(const float* __restrict__ p0,
        const float* __restrict__ p1,
        const float* __restrict__ p2,
        const float* __restrict__ targets,
        const float* __restrict__ anchors,
        int B, int N, int nDense, float* out) {
    int lane = threadIdx.x & 31, w = threadIdx.x >> 5;
    __shared__ double sl[8], sn[8];

    if ((int)blockIdx.x < nDense) {
        // ---------------- dense noobj ----------------
        int t  = blockIdx.x * blockDim.x + threadIdx.x;
        int q1 = B * 3 * 169;              // scale-1 quads (== scale-0 elements)
        int Q  = B * 3 * 845;
        float sum = 0.f;
        if (t < Q) {
            if (t < q1) {
                int r = t / 169, qi = t - r * 169;
                size_t row = (size_t)((r / 3) * 255 + (r % 3) * 85 + 4);
                float4 v = *(const float4*)(p1 + row * 676 + qi * 4);
                sum = sp(v.x) + sp(v.y) + sp(v.z) + sp(v.w);
                sum += sp(p0[row * 169 + qi]);
            } else {
                int u = t - q1;
                int r = u / 676, qi = u - r * 676;
                size_t row = (size_t)((r / 3) * 255 + (r % 3) * 85 + 4);
                float4 v = *(const float4*)(p2 + row * 2704 + qi * 4);
                sum = sp(v.x) + sp(v.y) + sp(v.z) + sp(v.w);
            }
        }
        sum = warp_sum(sum);
        if (lane == 0) { sl[w] = 0.5 * (double)sum; sn[w] = 0.0; }
    } else {
        // ---------------- sparse correction ----------------
        int gw_id = (blockIdx.x - nDense) * 8 + w;
        int cnt = g_cnt;
        double contrib = 0.0, np = 0.0;
        if (gw_id < cnt) {
            int pk = g_list[gw_id];
            int s = (pk >> 20) & 3, b = (pk >> 14) & 63;
            int a = (pk >> 12) & 3, j = (pk >> 6) & 63, i = pk & 63;
            int H   = (s == 0) ? 13 : (s == 1) ? 26 : 52;
            int off = (s == 0) ? 0 : (s == 1) ? B * 3 * 169 : B * 3 * (169 + 676);
            int HW  = H * H;
            const float* pred = (s == 0) ? p0 : (s == 1) ? p1 : p2;
            int cell = off + (b * 3 + a) * HW + j * H + i;
            size_t base = ((size_t)(b * 255 + a * 85)) * HW + (size_t)j * H + i;

            int wn = g_winner[cell];                    // n+1, 0 = none
            float conf = pred[base + (size_t)4 * HW];

            if (wn > 0) {
                const float* tg = targets + (size_t)(b * N + (wn - 1)) * 5;
                int gcls = (int)tg[4];
                float lcls = 0.f;
                #pragma unroll
                for (int c = lane; c < NCLS; c += 32) {
                    float pc = pred[base + (size_t)(5 + c) * HW];
                    lcls += bcef(pc, (c == gcls) ? 1.f : 0.f);
                }
                lcls = warp_sum(lcls);
                if (lane == 0) {
                    float gx = tg[0], gy = tg[1], gww = tg[2], ghh = tg[3];
                    int ai = (2 - s) * 3 + a;
                    float aw = anchors[ai * 2 + 0] * (1.f / 416.f);
                    float ah = anchors[ai * 2 + 1] * (1.f / 416.f);
                    float tx = gx * H - i, ty = gy * H - j;
                    float tw = logf(gww / aw), th = logf(ghh / ah);
                    float px = pred[base];
                    float py = pred[base + (size_t)1 * HW];
                    float pw = pred[base + (size_t)2 * HW];
                    float ph = pred[base + (size_t)3 * HW];
                    float lcoord = bcef(px, tx) + bcef(py, ty)
                                 + (pw - tw) * (pw - tw) + (ph - th) * (ph - th);
                    contrib = (double)(5.0f * lcoord + sp(-conf) + lcls)
                            - 0.5 * (double)sp(conf);
                    np = 1.0;
                }
            } else if (lane == 0) {
                contrib = -0.5 * (double)sp(conf);      // ignore-only cell
            }
            // restore scratch invariant for next call
            if (lane == 0) {
                g_winner[cell] = 0;
                atomicAnd(&g_bits[cell >> 5], ~(1u << (cell & 31)));
            }
        }
        if (lane == 0) { sl[w] = contrib; sn[w] = np; }
    }

    __syncthreads();
    if (threadIdx.x == 0) {
        double L = 0.0, P = 0.0;
        #pragma unroll
        for (int k = 0; k < 8; k++) { L += sl[k]; P += sn[k]; }
        if (L != 0.0) atomicAdd(&g_acc[0], L);
        if (P != 0.0) atomicAdd(&g_acc[1], P);
        __threadfence();
        int prev = atomicAdd(&g_done, 1);
        if (prev == (int)gridDim.x - 1) {
            // all blocks' contributions are globally visible
            double l = atomicAdd(&g_acc[0], 0.0);
            double n = atomicAdd(&g_acc[1], 0.0);
            out[0] = (float)((n > 0.0) ? l / n : l / (double)B);
            g_acc[0] = 0.0; g_acc[1] = 0.0;
            g_cnt = 0; g_done = 0;
        }
    }
}

extern "C" void kernel_launch(void* const* d_in, const int* in_sizes, int n_in,
                              void* d_out, int out_size) {
    const float* p0      = (const float*)d_in[0];
    const float* p1      = (const float*)d_in[1];
    const float* p2      = (const float*)d_in[2];
    const float* targets = (const float*)d_in[3];
    const unsigned char* gvalid = (const unsigned char*)d_in[4];
    const float* anchors = (const float*)d_in[5];
    float* out = (float*)d_out;

    int B = in_sizes[0] / (255 * 13 * 13);
    int N = in_sizes[3] / (B * 5);
    if (B > MAXB) B = MAXB;   // scratch bound (shapes fixed at B=32)

    int tgt_items = 3 * B * N;
    int nDense    = (B * 3 * 845 + 255) / 256;          // dense quad blocks
    int nSparse   = (3 * 3 * B * N + 7) / 8;            // 8 warps/block, 1 cell/warp

    k_targets<<<(tgt_items + 127) / 128, 128>>>(targets, gvalid, anchors, B, N);
    k_fused  <<<nDense + nSparse, 256>>>(p0, p1, p2, targets, anchors,
                                         B, N, nDense, out);
}